// round 14
// baseline (speedup 1.0000x reference)
#include <cuda_runtime.h>
#include <cuda_bf16.h>
#include <cstdint>

#define NN 50000
#define NE 800000

// ---------------- scratch ----------------
__device__ float g_inl[NN * 128];
__device__ float g_im[NE * 128];
__device__ float g_curW[NE * 128];
__device__ float g_agg[NN * 128];
__device__ float g_aggW[NN * 128];
// bf16 weight tables: W^T layout [oc][k], hi table then lo table
__device__ uint16_t g_wc[2 * 16384];
__device__ uint16_t g_wn[2 * 16384];
__device__ uint16_t g_wo[2 * 16384];
__device__ uint16_t g_we[2 * 4096];   // [oc=128][k=32]

// --- 1-CTA layout (big L1 share) for gather-heavy / node kernels ---
#define XS4 132
#define LO4 (128 * 132)
#define SMEM4 (2 * 128 * 132 * 4)      // 135168 B

// --- 2-CTA layout for compute-dense k_first ---
#define XST 68
#define BLO2 (128 * XST)
#define DOFF (2 * 128 * XST)
#define DST 132
#define SMEM5 ((DOFF + 64 * DST) * 4)  // 103424 B

// ---------------- helpers ----------------
__device__ __forceinline__ uint32_t smem_u32(const void* p) {
    uint32_t a;
    asm("{ .reg .u64 t; cvta.to.shared.u64 t, %1; cvt.u32.u64 %0, t; }" : "=r"(a) : "l"(p));
    return a;
}
__device__ __forceinline__ void ldm4(uint32_t* r, uint32_t addr) {
    asm volatile("ldmatrix.sync.aligned.m8n8.x4.shared.b16 {%0,%1,%2,%3}, [%4];"
                 : "=r"(r[0]), "=r"(r[1]), "=r"(r[2]), "=r"(r[3]) : "r"(addr));
}
__device__ __forceinline__ void mma_bf16(float* d, const uint32_t* a, uint32_t b0, uint32_t b1) {
    asm volatile("mma.sync.aligned.m16n8k16.row.col.f32.bf16.bf16.f32 "
                 "{%0,%1,%2,%3}, {%4,%5,%6,%7}, {%8,%9}, {%0,%1,%2,%3};"
                 : "+f"(d[0]), "+f"(d[1]), "+f"(d[2]), "+f"(d[3])
                 : "r"(a[0]), "r"(a[1]), "r"(a[2]), "r"(a[3]), "r"(b0), "r"(b1));
}
__device__ __forceinline__ float4 relu4(float4 v) {
    v.x = fmaxf(v.x, 0.f); v.y = fmaxf(v.y, 0.f);
    v.z = fmaxf(v.z, 0.f); v.w = fmaxf(v.w, 0.f);
    return v;
}
__device__ __forceinline__ void red_add4(float* p, float4 v) {
    asm volatile("red.global.add.v4.f32 [%0], {%1,%2,%3,%4};"
                 :: "l"(p), "f"(v.x), "f"(v.y), "f"(v.z), "f"(v.w) : "memory");
}
__device__ __forceinline__ uint32_t pck(float a, float b) {   // low=a, high=b
    uint32_t r;
    asm("cvt.rn.bf16x2.f32 %0, %1, %2;" : "=r"(r) : "f"(b), "f"(a));
    return r;
}
__device__ __forceinline__ void split_f4(float4 v, uint32_t& h0, uint32_t& h1,
                                         uint32_t& l0, uint32_t& l1) {
    h0 = pck(v.x, v.y); h1 = pck(v.z, v.w);
    float a0 = __uint_as_float(h0 << 16);
    float a1 = __uint_as_float(h0 & 0xFFFF0000u);
    float a2 = __uint_as_float(h1 << 16);
    float a3 = __uint_as_float(h1 & 0xFFFF0000u);
    l0 = pck(v.x - a0, v.y - a1);
    l1 = pck(v.z - a2, v.w - a3);
}

// ======== 512-thread MMA stage: 8 warps over oc x 2 nt-halves ========
template <int NKT, int WS, int BLO>
__device__ __forceinline__ void mma_stage512(uint32_t sb, const uint32_t* w2h,
                                             const uint32_t* w2l, float* sout,
                                             int warp, int lane) {
    int wg = warp & 7, wq = warp >> 3;
    int q = lane >> 2, m4 = lane & 3;
    int oc = wg * 16 + q;
    uint32_t ah[NKT][4], al[NKT][4];
#pragma unroll
    for (int kt = 0; kt < NKT; kt++) {
        int b0 = oc * WS + kt * 8 + m4, b1 = (oc + 8) * WS + kt * 8 + m4;
        ah[kt][0] = w2h[b0];     ah[kt][1] = w2h[b1];
        ah[kt][2] = w2h[b0 + 4]; ah[kt][3] = w2h[b1 + 4];
        al[kt][0] = w2l[b0];     al[kt][1] = w2l[b1];
        al[kt][2] = w2l[b0 + 4]; al[kt][3] = w2l[b1 + 4];
    }
    float acc[8][4];
#pragma unroll
    for (int n8 = 0; n8 < 8; n8++)
#pragma unroll
        for (int i = 0; i < 4; i++) acc[n8][i] = 0.f;

    int j8 = lane & 7, sel = lane >> 3;
    uint32_t aoff = (sel >= 2 ? (uint32_t)BLO : 0u) + (uint32_t)j8 * XS4 + (sel & 1) * 4;
#pragma unroll
    for (int kt = 0; kt < NKT; kt++) {
#pragma unroll
        for (int n8 = 0; n8 < 8; n8++) {
            int nt = wq * 8 + n8;
            uint32_t b[4];
            ldm4(b, sb + (aoff + (uint32_t)nt * 8 * XS4 + (uint32_t)kt * 8) * 4);
            mma_bf16(acc[n8], ah[kt], b[0], b[1]);
            mma_bf16(acc[n8], al[kt], b[0], b[1]);
            mma_bf16(acc[n8], ah[kt], b[2], b[3]);
        }
    }
    __syncthreads();   // all B reads done before staging overwrites X region
#pragma unroll
    for (int n8 = 0; n8 < 8; n8++) {
        int e = (wq * 8 + n8) * 8 + m4 * 2;
        sout[e * XS4 + oc]           = acc[n8][0];
        sout[(e + 1) * XS4 + oc]     = acc[n8][1];
        sout[e * XS4 + oc + 8]       = acc[n8][2];
        sout[(e + 1) * XS4 + oc + 8] = acc[n8][3];
    }
    __syncthreads();
}

// ======== 2-CTA helpers for k_first ========
template <int NKT, int WS>
__device__ __forceinline__ void load_wfrags(const uint32_t* w2h, const uint32_t* w2l,
                                            uint32_t ah[][4], uint32_t al[][4],
                                            int warp, int lane) {
    int q = lane >> 2, m4 = lane & 3;
    int oc = warp * 16 + q;
#pragma unroll
    for (int kt = 0; kt < NKT; kt++) {
        int b0 = oc * WS + kt * 8 + m4, b1 = (oc + 8) * WS + kt * 8 + m4;
        ah[kt][0] = w2h[b0];     ah[kt][1] = w2h[b1];
        ah[kt][2] = w2h[b0 + 4]; ah[kt][3] = w2h[b1 + 4];
        al[kt][0] = w2l[b0];     al[kt][1] = w2l[b1];
        al[kt][2] = w2l[b0 + 4]; al[kt][3] = w2l[b1 + 4];
    }
}
template <int NKT, int BLOv>
__device__ __forceinline__ void mma_wave(uint32_t sb, const uint32_t ah[][4],
                                         const uint32_t al[][4], float* dst,
                                         int wave, int warp, int lane) {
    int q = lane >> 2, m4 = lane & 3, oc = warp * 16 + q;
    int j8 = lane & 7, sel = lane >> 3;
    uint32_t aoff = (sel >= 2 ? (uint32_t)BLOv : 0u) + (uint32_t)j8 * XST + (sel & 1) * 4u;
    float acc[8][4];
#pragma unroll
    for (int n8 = 0; n8 < 8; n8++)
#pragma unroll
        for (int i = 0; i < 4; i++) acc[n8][i] = 0.f;
#pragma unroll
    for (int kt = 0; kt < NKT; kt++) {
#pragma unroll
        for (int n8 = 0; n8 < 8; n8++) {
            int nt = wave * 8 + n8;
            uint32_t b[4];
            ldm4(b, sb + (aoff + (uint32_t)nt * 8 * XST + (uint32_t)kt * 8) * 4);
            mma_bf16(acc[n8], ah[kt], b[0], b[1]);
            mma_bf16(acc[n8], al[kt], b[0], b[1]);
            mma_bf16(acc[n8], ah[kt], b[2], b[3]);
        }
    }
#pragma unroll
    for (int n8 = 0; n8 < 8; n8++) {
        int e = n8 * 8 + m4 * 2;
        dst[e * DST + oc]           = acc[n8][0];
        dst[(e + 1) * DST + oc]     = acc[n8][1];
        dst[e * DST + oc + 8]       = acc[n8][2];
        dst[(e + 1) * DST + oc + 8] = acc[n8][3];
    }
}

// ---------------- prep / zero ----------------
__global__ void k_prep(const float* __restrict__ Wc, const float* __restrict__ Wn,
                       const float* __restrict__ Wo, const float* __restrict__ We) {
    int st = gridDim.x * blockDim.x;
    for (int idx = blockIdx.x * blockDim.x + threadIdx.x; idx < 16384; idx += st) {
        int k = idx >> 7, n = idx & 127;
        int pos = n * 128 + k;   // [oc][k]
        float v;
        __nv_bfloat16 hb;
        v = Wc[idx]; hb = __float2bfloat16_rn(v);
        g_wc[pos] = __bfloat16_as_ushort(hb);
        g_wc[16384 + pos] = __bfloat16_as_ushort(__float2bfloat16_rn(v - __bfloat162float(hb)));
        v = Wn[idx]; hb = __float2bfloat16_rn(v);
        g_wn[pos] = __bfloat16_as_ushort(hb);
        g_wn[16384 + pos] = __bfloat16_as_ushort(__float2bfloat16_rn(v - __bfloat162float(hb)));
        v = Wo[idx]; hb = __float2bfloat16_rn(v);
        g_wo[pos] = __bfloat16_as_ushort(hb);
        g_wo[16384 + pos] = __bfloat16_as_ushort(__float2bfloat16_rn(v - __bfloat162float(hb)));
    }
    for (int idx = blockIdx.x * blockDim.x + threadIdx.x; idx < 4096; idx += st) {
        int k = idx >> 7, n = idx & 127;      // k 0..31
        float v = We[k * 128 + n];
        __nv_bfloat16 hb = __float2bfloat16_rn(v);
        g_we[n * 32 + k] = __bfloat16_as_ushort(hb);
        g_we[4096 + n * 32 + k] =
            __bfloat16_as_ushort(__float2bfloat16_rn(v - __bfloat162float(hb)));
    }
}
__global__ void k_zero(float* out, int out_n) {
    int i = blockIdx.x * blockDim.x + threadIdx.x, st = gridDim.x * blockDim.x;
    float4 z = make_float4(0.f, 0.f, 0.f, 0.f);
    for (int j = i; j < NN * 32; j += st) reinterpret_cast<float4*>(g_agg)[j] = z;
    for (int j = i; j < out_n; j += st) out[j] = 0.f;
}

// ---------------- k_first (2 CTA/SM, batched epilogue gathers) ----------------
__global__ void __launch_bounds__(256, 2)
k_first(const float* __restrict__ ef, const float* __restrict__ be,
        const int* __restrict__ esrc, const int* __restrict__ edst) {
    extern __shared__ uint32_t sx[];
    uint32_t sb = smem_u32(sx);
    float* dstage = reinterpret_cast<float*>(sx + DOFF);
    int t = threadIdx.x, warp = t >> 5, lane = t & 31;
    {   // split edge_feat rows into X region (hi cols 0..15 u32, lo at +16)
        int r = t >> 1, h = t & 1;
        int e = blockIdx.x * 128 + r;
        const float4* efp = reinterpret_cast<const float4*>(ef + (size_t)e * 32 + h * 16);
        uint32_t* eh = sx + r * XST + h * 8;
        uint32_t* el = eh + 16;
#pragma unroll
        for (int j = 0; j < 4; j++) {
            uint32_t h0, h1, l0, l1;
            split_f4(efp[j], h0, h1, l0, l1);
            eh[2 * j] = h0; eh[2 * j + 1] = h1;
            el[2 * j] = l0; el[2 * j + 1] = l1;
        }
    }
    uint32_t ahe[2][4], ale[2][4];
    load_wfrags<2, 16>(reinterpret_cast<const uint32_t*>(g_we),
                       reinterpret_cast<const uint32_t*>(g_we) + 2048, ahe, ale, warp, lane);
    __syncthreads();
    const float4* be4 = reinterpret_cast<const float4*>(be);
#pragma unroll 1
    for (int w = 0; w < 2; w++) {
        mma_wave<2, 16>(sb, ahe, ale, dstage, w, warp, lane);
        __syncthreads();
        int rr = t >> 2, qh = t & 3;
        int rl = w * 64 + rr;
        int e2 = blockIdx.x * 128 + rl;
        int s2 = esrc[e2], d2 = edst[e2];
        const float* drow = dstage + rr * DST;
        const float4* il4 = reinterpret_cast<const float4*>(g_inl + (size_t)s2 * 128);
        float4* imo4 = reinterpret_cast<float4*>(g_im + (size_t)e2 * 128);
        float* aggp = g_agg + (size_t)d2 * 128;
        uint32_t* xh = sx + rl * XST;
        uint32_t* xl2 = xh + BLO2;
        // batch the 8 global gather loads first (max MLP)
        float4 il[8];
#pragma unroll
        for (int j = 0; j < 8; j++) {
            int c4 = qh * 8 + ((j + 2 * qh) & 7);
            il[j] = il4[c4];
        }
#pragma unroll
        for (int j = 0; j < 8; j++) {
            int c4 = qh * 8 + ((j + 2 * qh) & 7);
            float4 d = *reinterpret_cast<const float4*>(drow + c4 * 4);
            float4 a = il[j], b = be4[c4];
            float4 m = make_float4(d.x + a.x + b.x, d.y + a.y + b.y,
                                   d.z + a.z + b.z, d.w + a.w + b.w);
            imo4[c4] = m;
            float4 xx = relu4(m);
            red_add4(aggp + c4 * 4, xx);
            uint32_t h0, h1, l0, l1;
            split_f4(xx, h0, h1, l0, l1);
            xh[c4 * 2] = h0; xh[c4 * 2 + 1] = h1;
            xl2[c4 * 2] = l0; xl2[c4 * 2 + 1] = l1;
        }
        __syncthreads();
    }
    // GEMM2: curW = x @ Wc
    uint32_t ah[8][4], al[8][4];
    load_wfrags<8, 64>(reinterpret_cast<const uint32_t*>(g_wc),
                       reinterpret_cast<const uint32_t*>(g_wc) + 8192, ah, al, warp, lane);
#pragma unroll 1
    for (int w = 0; w < 2; w++) {
        mma_wave<8, BLO2>(sb, ah, al, dstage, w, warp, lane);
        __syncthreads();
        int rr = t >> 2, qh = t & 3;
        int e2 = blockIdx.x * 128 + w * 64 + rr;
        float4* cww = reinterpret_cast<float4*>(g_curW + (size_t)e2 * 128);
        const float* drow = dstage + rr * DST;
#pragma unroll
        for (int j = 0; j < 8; j++) {
            int c4 = qh * 8 + ((j + 2 * qh) & 7);
            cww[c4] = *reinterpret_cast<const float4*>(drow + c4 * 4);
        }
        __syncthreads();
    }
}

// ---------------- k_iter (1 CTA/SM, 512 threads, batched phase-A loads) ----------------
__global__ void __launch_bounds__(512)
k_iter(const float* __restrict__ bc, const int* __restrict__ esrc,
       const int* __restrict__ edst) {
    extern __shared__ uint8_t sm[];
    uint32_t sb = smem_u32(sm);
    int t = threadIdx.x, r = t >> 2, q = t & 3;   // 4 threads per edge row
    int e = blockIdx.x * 128 + r;
    int src = esrc[e], dst = edst[e];
    {
        const float4* aw4 = reinterpret_cast<const float4*>(g_aggW + (size_t)src * 128);
        const float4* cw4 = reinterpret_cast<const float4*>(g_curW + (size_t)(e ^ 1) * 128);
        const float4* im4 = reinterpret_cast<const float4*>(g_im + (size_t)e * 128);
        const float4* bp = reinterpret_cast<const float4*>(bc);
        float* aggp = g_agg + (size_t)dst * 128;
        uint32_t* xh = reinterpret_cast<uint32_t*>(sm) + r * XS4;
        uint32_t* xl = xh + LO4;
        // batch all 24 independent global loads first (max MLP)
        float4 aw[8], cw[8], im[8];
#pragma unroll
        for (int j = 0; j < 8; j++) aw[j] = aw4[q + 4 * j];
#pragma unroll
        for (int j = 0; j < 8; j++) cw[j] = cw4[q + 4 * j];
#pragma unroll
        for (int j = 0; j < 8; j++) im[j] = im4[q + 4 * j];
#pragma unroll
        for (int j = 0; j < 8; j++) {
            int c4 = q + 4 * j;
            float4 b = bp[c4];
            float4 x = relu4(make_float4(aw[j].x - cw[j].x + im[j].x + b.x,
                                         aw[j].y - cw[j].y + im[j].y + b.y,
                                         aw[j].z - cw[j].z + im[j].z + b.z,
                                         aw[j].w - cw[j].w + im[j].w + b.w));
            red_add4(aggp + 4 * c4, x);
            uint32_t h0, h1, l0, l1;
            split_f4(x, h0, h1, l0, l1);
            xh[2 * c4] = h0; xh[2 * c4 + 1] = h1;
            xl[2 * c4] = l0; xl[2 * c4 + 1] = l1;
        }
    }
    __syncthreads();
    int warp = t >> 5, lane = t & 31;
    mma_stage512<8, 64, LO4>(sb, reinterpret_cast<const uint32_t*>(g_wc),
                             reinterpret_cast<const uint32_t*>(g_wc) + 8192,
                             reinterpret_cast<float*>(sm), warp, lane);
    {
        const float* drow = reinterpret_cast<float*>(sm) + r * XS4;
        float4* cwo = reinterpret_cast<float4*>(g_curW + (size_t)e * 128);
#pragma unroll
        for (int j = 0; j < 8; j++) {
            int c4 = q + 4 * j;
            cwo[c4] = *reinterpret_cast<const float4*>(drow + 4 * c4);
        }
    }
}

// last iteration: only x + scatter (batched loads)
__global__ void __launch_bounds__(512)
k_last(const float* __restrict__ bc, const int* __restrict__ esrc,
       const int* __restrict__ edst) {
    int t = threadIdx.x, r = t >> 2, q = t & 3;
    int e = blockIdx.x * 128 + r;
    int src = esrc[e], dst = edst[e];
    const float4* aw4 = reinterpret_cast<const float4*>(g_aggW + (size_t)src * 128);
    const float4* cw4 = reinterpret_cast<const float4*>(g_curW + (size_t)(e ^ 1) * 128);
    const float4* im4 = reinterpret_cast<const float4*>(g_im + (size_t)e * 128);
    const float4* bp = reinterpret_cast<const float4*>(bc);
    float* aggp = g_agg + (size_t)dst * 128;
    float4 aw[8], cw[8], im[8];
#pragma unroll
    for (int j = 0; j < 8; j++) aw[j] = aw4[q + 4 * j];
#pragma unroll
    for (int j = 0; j < 8; j++) cw[j] = cw4[q + 4 * j];
#pragma unroll
    for (int j = 0; j < 8; j++) im[j] = im4[q + 4 * j];
#pragma unroll
    for (int j = 0; j < 8; j++) {
        int c4 = q + 4 * j;
        float4 b = bp[c4];
        float4 v = make_float4(aw[j].x - cw[j].x + im[j].x + b.x,
                               aw[j].y - cw[j].y + im[j].y + b.y,
                               aw[j].z - cw[j].z + im[j].z + b.z,
                               aw[j].w - cw[j].w + im[j].w + b.w);
        red_add4(aggp + 4 * c4, relu4(v));
    }
}

// ---------------- node kernels (512 threads, 1 CTA/SM, batched loads) ----------------
__global__ void __launch_bounds__(512)
k_nlin(const float* __restrict__ nf, const float* __restrict__ bn) {
    extern __shared__ uint8_t sm[];
    uint32_t sb = smem_u32(sm);
    int t = threadIdx.x, r = t >> 2, q = t & 3;
    int n = blockIdx.x * 128 + r;
    bool v = n < NN;
    int nc = v ? n : 0;
    {
        const float4* xp = reinterpret_cast<const float4*>(nf + (size_t)nc * 128);
        uint32_t* xh = reinterpret_cast<uint32_t*>(sm) + r * XS4;
        uint32_t* xl = xh + LO4;
        float4 x[8];
#pragma unroll
        for (int j = 0; j < 8; j++) x[j] = xp[q + 4 * j];
#pragma unroll
        for (int j = 0; j < 8; j++) {
            int c4 = q + 4 * j;
            uint32_t h0, h1, l0, l1;
            split_f4(x[j], h0, h1, l0, l1);
            xh[2 * c4] = h0; xh[2 * c4 + 1] = h1;
            xl[2 * c4] = l0; xl[2 * c4 + 1] = l1;
        }
    }
    __syncthreads();
    int warp = t >> 5, lane = t & 31;
    mma_stage512<8, 64, LO4>(sb, reinterpret_cast<const uint32_t*>(g_wn),
                             reinterpret_cast<const uint32_t*>(g_wn) + 8192,
                             reinterpret_cast<float*>(sm), warp, lane);
    if (v) {
        const float* drow = reinterpret_cast<float*>(sm) + r * XS4;
        const float4* bp = reinterpret_cast<const float4*>(bn);
        float4* o = reinterpret_cast<float4*>(g_inl + (size_t)n * 128);
#pragma unroll
        for (int j = 0; j < 8; j++) {
            int c4 = q + 4 * j;
            float4 s = *reinterpret_cast<const float4*>(drow + 4 * c4);
            float4 b = bp[c4];
            o[c4] = make_float4(s.x + b.x, s.y + b.y, s.z + b.z, s.w + b.w);
        }
    }
}

__global__ void __launch_bounds__(512)
k_aggW() {
    extern __shared__ uint8_t sm[];
    uint32_t sb = smem_u32(sm);
    int t = threadIdx.x, r = t >> 2, q = t & 3;
    int n = blockIdx.x * 128 + r;
    bool v = n < NN;
    int nc = v ? n : 0;
    {
        float4* ap = reinterpret_cast<float4*>(g_agg + (size_t)nc * 128);
        const float4 z = make_float4(0.f, 0.f, 0.f, 0.f);
        uint32_t* xh = reinterpret_cast<uint32_t*>(sm) + r * XS4;
        uint32_t* xl = xh + LO4;
        float4 x[8];
#pragma unroll
        for (int j = 0; j < 8; j++) x[j] = ap[q + 4 * j];
#pragma unroll
        for (int j = 0; j < 8; j++) {
            int c4 = q + 4 * j;
            if (v) ap[c4] = z;   // reset for next scatter round
            uint32_t h0, h1, l0, l1;
            split_f4(x[j], h0, h1, l0, l1);
            xh[2 * c4] = h0; xh[2 * c4 + 1] = h1;
            xl[2 * c4] = l0; xl[2 * c4 + 1] = l1;
        }
    }
    __syncthreads();
    int warp = t >> 5, lane = t & 31;
    mma_stage512<8, 64, LO4>(sb, reinterpret_cast<const uint32_t*>(g_wc),
                             reinterpret_cast<const uint32_t*>(g_wc) + 8192,
                             reinterpret_cast<float*>(sm), warp, lane);
    if (v) {
        const float* drow = reinterpret_cast<float*>(sm) + r * XS4;
        float4* o = reinterpret_cast<float4*>(g_aggW + (size_t)n * 128);
#pragma unroll
        for (int j = 0; j < 8; j++) {
            int c4 = q + 4 * j;
            o[c4] = *reinterpret_cast<const float4*>(drow + 4 * c4);
        }
    }
}

__global__ void __launch_bounds__(512)
k_out(const float* __restrict__ bo, const int* __restrict__ gids,
      float* __restrict__ out) {
    extern __shared__ uint8_t sm[];
    uint32_t sb = smem_u32(sm);
    int t = threadIdx.x, r = t >> 2, q = t & 3;
    int n = blockIdx.x * 128 + r;
    bool v = n < NN;
    int nc = v ? n : 0;
    {
        const float4* ap = reinterpret_cast<const float4*>(g_agg + (size_t)nc * 128);
        uint32_t* xh = reinterpret_cast<uint32_t*>(sm) + r * XS4;
        uint32_t* xl = xh + LO4;
        float4 x[8];
#pragma unroll
        for (int j = 0; j < 8; j++) x[j] = ap[q + 4 * j];
#pragma unroll
        for (int j = 0; j < 8; j++) {
            int c4 = q + 4 * j;
            uint32_t h0, h1, l0, l1;
            split_f4(relu4(x[j]), h0, h1, l0, l1);
            xh[2 * c4] = h0; xh[2 * c4 + 1] = h1;
            xl[2 * c4] = l0; xl[2 * c4 + 1] = l1;
        }
    }
    __syncthreads();
    int warp = t >> 5, lane = t & 31;
    mma_stage512<8, 64, LO4>(sb, reinterpret_cast<const uint32_t*>(g_wo),
                             reinterpret_cast<const uint32_t*>(g_wo) + 8192,
                             reinterpret_cast<float*>(sm), warp, lane);
    if (v) {
        const float* drow = reinterpret_cast<float*>(sm) + r * XS4;
        const float4* bp = reinterpret_cast<const float4*>(bo);
        int gid = gids[n];
        float* op = out + (size_t)gid * 128;
#pragma unroll
        for (int j = 0; j < 8; j++) {
            int c4 = q + 4 * j;
            float4 s = *reinterpret_cast<const float4*>(drow + 4 * c4);
            float4 b = bp[c4];
            float4 y = make_float4(fmaxf(s.x + b.x, 0.f), fmaxf(s.y + b.y, 0.f),
                                   fmaxf(s.z + b.z, 0.f), fmaxf(s.w + b.w, 0.f));
            red_add4(op + 4 * c4, y);
        }
    }
}

extern "C" void kernel_launch(void* const* d_in, const int* in_sizes, int n_in,
                              void* d_out, int out_size) {
    const float* node_feat = (const float*)d_in[0];
    const float* edge_feat = (const float*)d_in[1];
    const float* Wn = (const float*)d_in[2];
    const float* bn = (const float*)d_in[3];
    const float* We = (const float*)d_in[4];
    const float* be = (const float*)d_in[5];
    const float* Wc = (const float*)d_in[6];
    const float* bc = (const float*)d_in[7];
    const float* Wo = (const float*)d_in[8];
    const float* bo = (const float*)d_in[9];
    const int* esrc = (const int*)d_in[10];
    const int* edst = (const int*)d_in[11];
    const int* gids = (const int*)d_in[12];
    float* out = (float*)d_out;

    cudaFuncSetAttribute(k_first, cudaFuncAttributeMaxDynamicSharedMemorySize, SMEM5);
    cudaFuncSetAttribute(k_iter,  cudaFuncAttributeMaxDynamicSharedMemorySize, SMEM4);
    cudaFuncSetAttribute(k_nlin,  cudaFuncAttributeMaxDynamicSharedMemorySize, SMEM4);
    cudaFuncSetAttribute(k_aggW,  cudaFuncAttributeMaxDynamicSharedMemorySize, SMEM4);
    cudaFuncSetAttribute(k_out,   cudaFuncAttributeMaxDynamicSharedMemorySize, SMEM4);

    const int NBN = (NN + 127) / 128;   // 391
    const int NBE = NE / 128;           // 6250

    k_zero<<<400, 256>>>(out, out_size);
    k_prep<<<64, 256>>>(Wc, Wn, Wo, We);
    k_nlin<<<NBN, 512, SMEM4>>>(node_feat, bn);
    k_first<<<NBE, 256, SMEM5>>>(edge_feat, be, esrc, edst);
    for (int it = 0; it < 3; it++) {
        k_aggW<<<NBN, 512, SMEM4>>>();
        if (it < 2)
            k_iter<<<NBE, 512, SMEM4>>>(bc, esrc, edst);
        else
            k_last<<<NBE, 512>>>(bc, esrc, edst);
    }
    k_out<<<NBN, 512, SMEM4>>>(bo, gids, out);
}

// round 15
// speedup vs baseline: 1.0190x; 1.0190x over previous
#include <cuda_runtime.h>
#include <cuda_bf16.h>
#include <cstdint>

#define NN 50000
#define NE 800000

// ---------------- scratch ----------------
__device__ float g_inl[NN * 128];
__device__ float g_im[NE * 128];
__device__ float g_curW[NE * 128];
__device__ float g_agg[NN * 128];
__device__ float g_aggW[NN * 128];
// bf16 weight tables: W^T layout [oc][k], hi table then lo table
__device__ uint16_t g_wc[2 * 16384];
__device__ uint16_t g_wn[2 * 16384];
__device__ uint16_t g_wo[2 * 16384];
__device__ uint16_t g_we[2 * 4096];   // [oc=128][k=32]

// --- 1-CTA layout (big L1 share) for gather-heavy / node kernels ---
#define XS4 132
#define LO4 (128 * 132)
#define SMEM4 (2 * 128 * 132 * 4)      // 135168 B

// --- 2-CTA layout for compute-dense k_first ---
#define XST 68
#define BLO2 (128 * XST)
#define DOFF (2 * 128 * XST)
#define DST 132
#define SMEM5 ((DOFF + 64 * DST) * 4)  // 103424 B

// ---------------- helpers ----------------
__device__ __forceinline__ uint32_t smem_u32(const void* p) {
    uint32_t a;
    asm("{ .reg .u64 t; cvta.to.shared.u64 t, %1; cvt.u32.u64 %0, t; }" : "=r"(a) : "l"(p));
    return a;
}
__device__ __forceinline__ void ldm4(uint32_t* r, uint32_t addr) {
    asm volatile("ldmatrix.sync.aligned.m8n8.x4.shared.b16 {%0,%1,%2,%3}, [%4];"
                 : "=r"(r[0]), "=r"(r[1]), "=r"(r[2]), "=r"(r[3]) : "r"(addr));
}
__device__ __forceinline__ void mma_bf16(float* d, const uint32_t* a, uint32_t b0, uint32_t b1) {
    asm volatile("mma.sync.aligned.m16n8k16.row.col.f32.bf16.bf16.f32 "
                 "{%0,%1,%2,%3}, {%4,%5,%6,%7}, {%8,%9}, {%0,%1,%2,%3};"
                 : "+f"(d[0]), "+f"(d[1]), "+f"(d[2]), "+f"(d[3])
                 : "r"(a[0]), "r"(a[1]), "r"(a[2]), "r"(a[3]), "r"(b0), "r"(b1));
}
__device__ __forceinline__ float4 relu4(float4 v) {
    v.x = fmaxf(v.x, 0.f); v.y = fmaxf(v.y, 0.f);
    v.z = fmaxf(v.z, 0.f); v.w = fmaxf(v.w, 0.f);
    return v;
}
__device__ __forceinline__ void red_add4(float* p, float4 v) {
    asm volatile("red.global.add.v4.f32 [%0], {%1,%2,%3,%4};"
                 :: "l"(p), "f"(v.x), "f"(v.y), "f"(v.z), "f"(v.w) : "memory");
}
__device__ __forceinline__ uint32_t pck(float a, float b) {   // low=a, high=b
    uint32_t r;
    asm("cvt.rn.bf16x2.f32 %0, %1, %2;" : "=r"(r) : "f"(b), "f"(a));
    return r;
}
__device__ __forceinline__ void split_f4(float4 v, uint32_t& h0, uint32_t& h1,
                                         uint32_t& l0, uint32_t& l1) {
    h0 = pck(v.x, v.y); h1 = pck(v.z, v.w);
    float a0 = __uint_as_float(h0 << 16);
    float a1 = __uint_as_float(h0 & 0xFFFF0000u);
    float a2 = __uint_as_float(h1 << 16);
    float a3 = __uint_as_float(h1 & 0xFFFF0000u);
    l0 = pck(v.x - a0, v.y - a1);
    l1 = pck(v.z - a2, v.w - a3);
}

// ======== 512-thread MMA stage: 8 warps over oc x 2 nt-halves ========
template <int NKT, int WS, int BLO>
__device__ __forceinline__ void mma_stage512(uint32_t sb, const uint32_t* w2h,
                                             const uint32_t* w2l, float* sout,
                                             int warp, int lane) {
    int wg = warp & 7, wq = warp >> 3;
    int q = lane >> 2, m4 = lane & 3;
    int oc = wg * 16 + q;
    uint32_t ah[NKT][4], al[NKT][4];
#pragma unroll
    for (int kt = 0; kt < NKT; kt++) {
        int b0 = oc * WS + kt * 8 + m4, b1 = (oc + 8) * WS + kt * 8 + m4;
        ah[kt][0] = w2h[b0];     ah[kt][1] = w2h[b1];
        ah[kt][2] = w2h[b0 + 4]; ah[kt][3] = w2h[b1 + 4];
        al[kt][0] = w2l[b0];     al[kt][1] = w2l[b1];
        al[kt][2] = w2l[b0 + 4]; al[kt][3] = w2l[b1 + 4];
    }
    float acc[8][4];
#pragma unroll
    for (int n8 = 0; n8 < 8; n8++)
#pragma unroll
        for (int i = 0; i < 4; i++) acc[n8][i] = 0.f;

    int j8 = lane & 7, sel = lane >> 3;
    uint32_t aoff = (sel >= 2 ? (uint32_t)BLO : 0u) + (uint32_t)j8 * XS4 + (sel & 1) * 4;
#pragma unroll
    for (int kt = 0; kt < NKT; kt++) {
#pragma unroll
        for (int n8 = 0; n8 < 8; n8++) {
            int nt = wq * 8 + n8;
            uint32_t b[4];
            ldm4(b, sb + (aoff + (uint32_t)nt * 8 * XS4 + (uint32_t)kt * 8) * 4);
            mma_bf16(acc[n8], ah[kt], b[0], b[1]);
            mma_bf16(acc[n8], al[kt], b[0], b[1]);
            mma_bf16(acc[n8], ah[kt], b[2], b[3]);
        }
    }
    __syncthreads();   // all B reads done before staging overwrites X region
#pragma unroll
    for (int n8 = 0; n8 < 8; n8++) {
        int e = (wq * 8 + n8) * 8 + m4 * 2;
        sout[e * XS4 + oc]           = acc[n8][0];
        sout[(e + 1) * XS4 + oc]     = acc[n8][1];
        sout[e * XS4 + oc + 8]       = acc[n8][2];
        sout[(e + 1) * XS4 + oc + 8] = acc[n8][3];
    }
    __syncthreads();
}

// ======== 2-CTA helpers for k_first ========
template <int NKT, int WS>
__device__ __forceinline__ void load_wfrags(const uint32_t* w2h, const uint32_t* w2l,
                                            uint32_t ah[][4], uint32_t al[][4],
                                            int warp, int lane) {
    int q = lane >> 2, m4 = lane & 3;
    int oc = warp * 16 + q;
#pragma unroll
    for (int kt = 0; kt < NKT; kt++) {
        int b0 = oc * WS + kt * 8 + m4, b1 = (oc + 8) * WS + kt * 8 + m4;
        ah[kt][0] = w2h[b0];     ah[kt][1] = w2h[b1];
        ah[kt][2] = w2h[b0 + 4]; ah[kt][3] = w2h[b1 + 4];
        al[kt][0] = w2l[b0];     al[kt][1] = w2l[b1];
        al[kt][2] = w2l[b0 + 4]; al[kt][3] = w2l[b1 + 4];
    }
}
template <int NKT, int BLOv>
__device__ __forceinline__ void mma_wave(uint32_t sb, const uint32_t ah[][4],
                                         const uint32_t al[][4], float* dst,
                                         int wave, int warp, int lane) {
    int q = lane >> 2, m4 = lane & 3, oc = warp * 16 + q;
    int j8 = lane & 7, sel = lane >> 3;
    uint32_t aoff = (sel >= 2 ? (uint32_t)BLOv : 0u) + (uint32_t)j8 * XST + (sel & 1) * 4u;
    float acc[8][4];
#pragma unroll
    for (int n8 = 0; n8 < 8; n8++)
#pragma unroll
        for (int i = 0; i < 4; i++) acc[n8][i] = 0.f;
#pragma unroll
    for (int kt = 0; kt < NKT; kt++) {
#pragma unroll
        for (int n8 = 0; n8 < 8; n8++) {
            int nt = wave * 8 + n8;
            uint32_t b[4];
            ldm4(b, sb + (aoff + (uint32_t)nt * 8 * XST + (uint32_t)kt * 8) * 4);
            mma_bf16(acc[n8], ah[kt], b[0], b[1]);
            mma_bf16(acc[n8], al[kt], b[0], b[1]);
            mma_bf16(acc[n8], ah[kt], b[2], b[3]);
        }
    }
#pragma unroll
    for (int n8 = 0; n8 < 8; n8++) {
        int e = n8 * 8 + m4 * 2;
        dst[e * DST + oc]           = acc[n8][0];
        dst[(e + 1) * DST + oc]     = acc[n8][1];
        dst[e * DST + oc + 8]       = acc[n8][2];
        dst[(e + 1) * DST + oc + 8] = acc[n8][3];
    }
}

// ---------------- prep / zero ----------------
__global__ void k_prep(const float* __restrict__ Wc, const float* __restrict__ Wn,
                       const float* __restrict__ Wo, const float* __restrict__ We) {
    int st = gridDim.x * blockDim.x;
    for (int idx = blockIdx.x * blockDim.x + threadIdx.x; idx < 16384; idx += st) {
        int k = idx >> 7, n = idx & 127;
        int pos = n * 128 + k;   // [oc][k]
        float v;
        __nv_bfloat16 hb;
        v = Wc[idx]; hb = __float2bfloat16_rn(v);
        g_wc[pos] = __bfloat16_as_ushort(hb);
        g_wc[16384 + pos] = __bfloat16_as_ushort(__float2bfloat16_rn(v - __bfloat162float(hb)));
        v = Wn[idx]; hb = __float2bfloat16_rn(v);
        g_wn[pos] = __bfloat16_as_ushort(hb);
        g_wn[16384 + pos] = __bfloat16_as_ushort(__float2bfloat16_rn(v - __bfloat162float(hb)));
        v = Wo[idx]; hb = __float2bfloat16_rn(v);
        g_wo[pos] = __bfloat16_as_ushort(hb);
        g_wo[16384 + pos] = __bfloat16_as_ushort(__float2bfloat16_rn(v - __bfloat162float(hb)));
    }
    for (int idx = blockIdx.x * blockDim.x + threadIdx.x; idx < 4096; idx += st) {
        int k = idx >> 7, n = idx & 127;      // k 0..31
        float v = We[k * 128 + n];
        __nv_bfloat16 hb = __float2bfloat16_rn(v);
        g_we[n * 32 + k] = __bfloat16_as_ushort(hb);
        g_we[4096 + n * 32 + k] =
            __bfloat16_as_ushort(__float2bfloat16_rn(v - __bfloat162float(hb)));
    }
}
__global__ void k_zero(float* out, int out_n) {
    int i = blockIdx.x * blockDim.x + threadIdx.x, st = gridDim.x * blockDim.x;
    float4 z = make_float4(0.f, 0.f, 0.f, 0.f);
    for (int j = i; j < NN * 32; j += st) reinterpret_cast<float4*>(g_agg)[j] = z;
    for (int j = i; j < out_n; j += st) out[j] = 0.f;
}

// ---------------- k_first (2 CTA/SM, R13/R11 form) ----------------
__global__ void __launch_bounds__(256, 2)
k_first(const float* __restrict__ ef, const float* __restrict__ be,
        const int* __restrict__ esrc, const int* __restrict__ edst) {
    extern __shared__ uint32_t sx[];
    uint32_t sb = smem_u32(sx);
    float* dstage = reinterpret_cast<float*>(sx + DOFF);
    int t = threadIdx.x, warp = t >> 5, lane = t & 31;
    {   // split edge_feat rows into X region (hi cols 0..15 u32, lo at +16)
        int r = t >> 1, h = t & 1;
        int e = blockIdx.x * 128 + r;
        const float4* efp = reinterpret_cast<const float4*>(ef + (size_t)e * 32 + h * 16);
        uint32_t* eh = sx + r * XST + h * 8;
        uint32_t* el = eh + 16;
#pragma unroll
        for (int j = 0; j < 4; j++) {
            uint32_t h0, h1, l0, l1;
            split_f4(efp[j], h0, h1, l0, l1);
            eh[2 * j] = h0; eh[2 * j + 1] = h1;
            el[2 * j] = l0; el[2 * j + 1] = l1;
        }
    }
    uint32_t ahe[2][4], ale[2][4];
    load_wfrags<2, 16>(reinterpret_cast<const uint32_t*>(g_we),
                       reinterpret_cast<const uint32_t*>(g_we) + 2048, ahe, ale, warp, lane);
    __syncthreads();
    const float4* be4 = reinterpret_cast<const float4*>(be);
#pragma unroll 1
    for (int w = 0; w < 2; w++) {
        mma_wave<2, 16>(sb, ahe, ale, dstage, w, warp, lane);
        __syncthreads();
        int rr = t >> 2, qh = t & 3;
        int rl = w * 64 + rr;
        int e2 = blockIdx.x * 128 + rl;
        int s2 = esrc[e2], d2 = edst[e2];
        const float* drow = dstage + rr * DST;
        const float4* il4 = reinterpret_cast<const float4*>(g_inl + (size_t)s2 * 128);
        float4* imo4 = reinterpret_cast<float4*>(g_im + (size_t)e2 * 128);
        float* aggp = g_agg + (size_t)d2 * 128;
        uint32_t* xh = sx + rl * XST;
        uint32_t* xl2 = xh + BLO2;
#pragma unroll
        for (int j = 0; j < 8; j++) {
            int c4 = qh * 8 + ((j + 2 * qh) & 7);
            float4 d = *reinterpret_cast<const float4*>(drow + c4 * 4);
            float4 a = il4[c4], b = be4[c4];
            float4 m = make_float4(d.x + a.x + b.x, d.y + a.y + b.y,
                                   d.z + a.z + b.z, d.w + a.w + b.w);
            imo4[c4] = m;
            float4 xx = relu4(m);
            red_add4(aggp + c4 * 4, xx);
            uint32_t h0, h1, l0, l1;
            split_f4(xx, h0, h1, l0, l1);
            xh[c4 * 2] = h0; xh[c4 * 2 + 1] = h1;
            xl2[c4 * 2] = l0; xl2[c4 * 2 + 1] = l1;
        }
        __syncthreads();
    }
    // GEMM2: curW = x @ Wc
    uint32_t ah[8][4], al[8][4];
    load_wfrags<8, 64>(reinterpret_cast<const uint32_t*>(g_wc),
                       reinterpret_cast<const uint32_t*>(g_wc) + 8192, ah, al, warp, lane);
#pragma unroll 1
    for (int w = 0; w < 2; w++) {
        mma_wave<8, BLO2>(sb, ah, al, dstage, w, warp, lane);
        __syncthreads();
        int rr = t >> 2, qh = t & 3;
        int e2 = blockIdx.x * 128 + w * 64 + rr;
        float4* cww = reinterpret_cast<float4*>(g_curW + (size_t)e2 * 128);
        const float* drow = dstage + rr * DST;
#pragma unroll
        for (int j = 0; j < 8; j++) {
            int c4 = qh * 8 + ((j + 2 * qh) & 7);
            cww[c4] = *reinterpret_cast<const float4*>(drow + c4 * 4);
        }
        __syncthreads();
    }
}

// ---------------- k_iter (1 CTA/SM, 512 threads, batched phase-A loads) ----------------
__global__ void __launch_bounds__(512)
k_iter(const float* __restrict__ bc, const int* __restrict__ esrc,
       const int* __restrict__ edst) {
    extern __shared__ uint8_t sm[];
    uint32_t sb = smem_u32(sm);
    int t = threadIdx.x, r = t >> 2, q = t & 3;   // 4 threads per edge row
    int e = blockIdx.x * 128 + r;
    int src = esrc[e], dst = edst[e];
    {
        const float4* aw4 = reinterpret_cast<const float4*>(g_aggW + (size_t)src * 128);
        const float4* cw4 = reinterpret_cast<const float4*>(g_curW + (size_t)(e ^ 1) * 128);
        const float4* im4 = reinterpret_cast<const float4*>(g_im + (size_t)e * 128);
        const float4* bp = reinterpret_cast<const float4*>(bc);
        float* aggp = g_agg + (size_t)dst * 128;
        uint32_t* xh = reinterpret_cast<uint32_t*>(sm) + r * XS4;
        uint32_t* xl = xh + LO4;
        // batch all 24 independent global loads first (max MLP)
        float4 aw[8], cw[8], im[8];
#pragma unroll
        for (int j = 0; j < 8; j++) aw[j] = aw4[q + 4 * j];
#pragma unroll
        for (int j = 0; j < 8; j++) cw[j] = cw4[q + 4 * j];
#pragma unroll
        for (int j = 0; j < 8; j++) im[j] = im4[q + 4 * j];
#pragma unroll
        for (int j = 0; j < 8; j++) {
            int c4 = q + 4 * j;
            float4 b = bp[c4];
            float4 x = relu4(make_float4(aw[j].x - cw[j].x + im[j].x + b.x,
                                         aw[j].y - cw[j].y + im[j].y + b.y,
                                         aw[j].z - cw[j].z + im[j].z + b.z,
                                         aw[j].w - cw[j].w + im[j].w + b.w));
            red_add4(aggp + 4 * c4, x);
            uint32_t h0, h1, l0, l1;
            split_f4(x, h0, h1, l0, l1);
            xh[2 * c4] = h0; xh[2 * c4 + 1] = h1;
            xl[2 * c4] = l0; xl[2 * c4 + 1] = l1;
        }
    }
    __syncthreads();
    int warp = t >> 5, lane = t & 31;
    mma_stage512<8, 64, LO4>(sb, reinterpret_cast<const uint32_t*>(g_wc),
                             reinterpret_cast<const uint32_t*>(g_wc) + 8192,
                             reinterpret_cast<float*>(sm), warp, lane);
    {
        const float* drow = reinterpret_cast<float*>(sm) + r * XS4;
        float4* cwo = reinterpret_cast<float4*>(g_curW + (size_t)e * 128);
#pragma unroll
        for (int j = 0; j < 8; j++) {
            int c4 = q + 4 * j;
            cwo[c4] = *reinterpret_cast<const float4*>(drow + 4 * c4);
        }
    }
}

// last iteration: only x + scatter (batched loads)
__global__ void __launch_bounds__(512)
k_last(const float* __restrict__ bc, const int* __restrict__ esrc,
       const int* __restrict__ edst) {
    int t = threadIdx.x, r = t >> 2, q = t & 3;
    int e = blockIdx.x * 128 + r;
    int src = esrc[e], dst = edst[e];
    const float4* aw4 = reinterpret_cast<const float4*>(g_aggW + (size_t)src * 128);
    const float4* cw4 = reinterpret_cast<const float4*>(g_curW + (size_t)(e ^ 1) * 128);
    const float4* im4 = reinterpret_cast<const float4*>(g_im + (size_t)e * 128);
    const float4* bp = reinterpret_cast<const float4*>(bc);
    float* aggp = g_agg + (size_t)dst * 128;
    float4 aw[8], cw[8], im[8];
#pragma unroll
    for (int j = 0; j < 8; j++) aw[j] = aw4[q + 4 * j];
#pragma unroll
    for (int j = 0; j < 8; j++) cw[j] = cw4[q + 4 * j];
#pragma unroll
    for (int j = 0; j < 8; j++) im[j] = im4[q + 4 * j];
#pragma unroll
    for (int j = 0; j < 8; j++) {
        int c4 = q + 4 * j;
        float4 b = bp[c4];
        float4 v = make_float4(aw[j].x - cw[j].x + im[j].x + b.x,
                               aw[j].y - cw[j].y + im[j].y + b.y,
                               aw[j].z - cw[j].z + im[j].z + b.z,
                               aw[j].w - cw[j].w + im[j].w + b.w);
        red_add4(aggp + 4 * c4, relu4(v));
    }
}

// ---------------- node kernels (512 threads, 1 CTA/SM, batched loads) ----------------
__global__ void __launch_bounds__(512)
k_nlin(const float* __restrict__ nf, const float* __restrict__ bn) {
    extern __shared__ uint8_t sm[];
    uint32_t sb = smem_u32(sm);
    int t = threadIdx.x, r = t >> 2, q = t & 3;
    int n = blockIdx.x * 128 + r;
    bool v = n < NN;
    int nc = v ? n : 0;
    {
        const float4* xp = reinterpret_cast<const float4*>(nf + (size_t)nc * 128);
        uint32_t* xh = reinterpret_cast<uint32_t*>(sm) + r * XS4;
        uint32_t* xl = xh + LO4;
        float4 x[8];
#pragma unroll
        for (int j = 0; j < 8; j++) x[j] = xp[q + 4 * j];
#pragma unroll
        for (int j = 0; j < 8; j++) {
            int c4 = q + 4 * j;
            uint32_t h0, h1, l0, l1;
            split_f4(x[j], h0, h1, l0, l1);
            xh[2 * c4] = h0; xh[2 * c4 + 1] = h1;
            xl[2 * c4] = l0; xl[2 * c4 + 1] = l1;
        }
    }
    __syncthreads();
    int warp = t >> 5, lane = t & 31;
    mma_stage512<8, 64, LO4>(sb, reinterpret_cast<const uint32_t*>(g_wn),
                             reinterpret_cast<const uint32_t*>(g_wn) + 8192,
                             reinterpret_cast<float*>(sm), warp, lane);
    if (v) {
        const float* drow = reinterpret_cast<float*>(sm) + r * XS4;
        const float4* bp = reinterpret_cast<const float4*>(bn);
        float4* o = reinterpret_cast<float4*>(g_inl + (size_t)n * 128);
#pragma unroll
        for (int j = 0; j < 8; j++) {
            int c4 = q + 4 * j;
            float4 s = *reinterpret_cast<const float4*>(drow + 4 * c4);
            float4 b = bp[c4];
            o[c4] = make_float4(s.x + b.x, s.y + b.y, s.z + b.z, s.w + b.w);
        }
    }
}

__global__ void __launch_bounds__(512)
k_aggW() {
    extern __shared__ uint8_t sm[];
    uint32_t sb = smem_u32(sm);
    int t = threadIdx.x, r = t >> 2, q = t & 3;
    int n = blockIdx.x * 128 + r;
    bool v = n < NN;
    int nc = v ? n : 0;
    {
        float4* ap = reinterpret_cast<float4*>(g_agg + (size_t)nc * 128);
        const float4 z = make_float4(0.f, 0.f, 0.f, 0.f);
        uint32_t* xh = reinterpret_cast<uint32_t*>(sm) + r * XS4;
        uint32_t* xl = xh + LO4;
        float4 x[8];
#pragma unroll
        for (int j = 0; j < 8; j++) x[j] = ap[q + 4 * j];
#pragma unroll
        for (int j = 0; j < 8; j++) {
            int c4 = q + 4 * j;
            if (v) ap[c4] = z;   // reset for next scatter round
            uint32_t h0, h1, l0, l1;
            split_f4(x[j], h0, h1, l0, l1);
            xh[2 * c4] = h0; xh[2 * c4 + 1] = h1;
            xl[2 * c4] = l0; xl[2 * c4 + 1] = l1;
        }
    }
    __syncthreads();
    int warp = t >> 5, lane = t & 31;
    mma_stage512<8, 64, LO4>(sb, reinterpret_cast<const uint32_t*>(g_wc),
                             reinterpret_cast<const uint32_t*>(g_wc) + 8192,
                             reinterpret_cast<float*>(sm), warp, lane);
    if (v) {
        const float* drow = reinterpret_cast<float*>(sm) + r * XS4;
        float4* o = reinterpret_cast<float4*>(g_aggW + (size_t)n * 128);
#pragma unroll
        for (int j = 0; j < 8; j++) {
            int c4 = q + 4 * j;
            o[c4] = *reinterpret_cast<const float4*>(drow + 4 * c4);
        }
    }
}

__global__ void __launch_bounds__(512)
k_out(const float* __restrict__ bo, const int* __restrict__ gids,
      float* __restrict__ out) {
    extern __shared__ uint8_t sm[];
    uint32_t sb = smem_u32(sm);
    int t = threadIdx.x, r = t >> 2, q = t & 3;
    int n = blockIdx.x * 128 + r;
    bool v = n < NN;
    int nc = v ? n : 0;
    {
        const float4* ap = reinterpret_cast<const float4*>(g_agg + (size_t)nc * 128);
        uint32_t* xh = reinterpret_cast<uint32_t*>(sm) + r * XS4;
        uint32_t* xl = xh + LO4;
        float4 x[8];
#pragma unroll
        for (int j = 0; j < 8; j++) x[j] = ap[q + 4 * j];
#pragma unroll
        for (int j = 0; j < 8; j++) {
            int c4 = q + 4 * j;
            uint32_t h0, h1, l0, l1;
            split_f4(relu4(x[j]), h0, h1, l0, l1);
            xh[2 * c4] = h0; xh[2 * c4 + 1] = h1;
            xl[2 * c4] = l0; xl[2 * c4 + 1] = l1;
        }
    }
    __syncthreads();
    int warp = t >> 5, lane = t & 31;
    mma_stage512<8, 64, LO4>(sb, reinterpret_cast<const uint32_t*>(g_wo),
                             reinterpret_cast<const uint32_t*>(g_wo) + 8192,
                             reinterpret_cast<float*>(sm), warp, lane);
    if (v) {
        const float* drow = reinterpret_cast<float*>(sm) + r * XS4;
        const float4* bp = reinterpret_cast<const float4*>(bo);
        int gid = gids[n];
        float* op = out + (size_t)gid * 128;
#pragma unroll
        for (int j = 0; j < 8; j++) {
            int c4 = q + 4 * j;
            float4 s = *reinterpret_cast<const float4*>(drow + 4 * c4);
            float4 b = bp[c4];
            float4 y = make_float4(fmaxf(s.x + b.x, 0.f), fmaxf(s.y + b.y, 0.f),
                                   fmaxf(s.z + b.z, 0.f), fmaxf(s.w + b.w, 0.f));
            red_add4(op + 4 * c4, y);
        }
    }
}

extern "C" void kernel_launch(void* const* d_in, const int* in_sizes, int n_in,
                              void* d_out, int out_size) {
    const float* node_feat = (const float*)d_in[0];
    const float* edge_feat = (const float*)d_in[1];
    const float* Wn = (const float*)d_in[2];
    const float* bn = (const float*)d_in[3];
    const float* We = (const float*)d_in[4];
    const float* be = (const float*)d_in[5];
    const float* Wc = (const float*)d_in[6];
    const float* bc = (const float*)d_in[7];
    const float* Wo = (const float*)d_in[8];
    const float* bo = (const float*)d_in[9];
    const int* esrc = (const int*)d_in[10];
    const int* edst = (const int*)d_in[11];
    const int* gids = (const int*)d_in[12];
    float* out = (float*)d_out;

    cudaFuncSetAttribute(k_first, cudaFuncAttributeMaxDynamicSharedMemorySize, SMEM5);
    cudaFuncSetAttribute(k_iter,  cudaFuncAttributeMaxDynamicSharedMemorySize, SMEM4);
    cudaFuncSetAttribute(k_nlin,  cudaFuncAttributeMaxDynamicSharedMemorySize, SMEM4);
    cudaFuncSetAttribute(k_aggW,  cudaFuncAttributeMaxDynamicSharedMemorySize, SMEM4);
    cudaFuncSetAttribute(k_out,   cudaFuncAttributeMaxDynamicSharedMemorySize, SMEM4);

    const int NBN = (NN + 127) / 128;   // 391
    const int NBE = NE / 128;           // 6250

    k_zero<<<400, 256>>>(out, out_size);
    k_prep<<<64, 256>>>(Wc, Wn, Wo, We);
    k_nlin<<<NBN, 512, SMEM4>>>(node_feat, bn);
    k_first<<<NBE, 256, SMEM5>>>(edge_feat, be, esrc, edst);
    for (int it = 0; it < 3; it++) {
        k_aggW<<<NBN, 512, SMEM4>>>();
        if (it < 2)
            k_iter<<<NBE, 512, SMEM4>>>(bc, esrc, edst);
        else
            k_last<<<NBE, 512>>>(bc, esrc, edst);
    }
    k_out<<<NBN, 512, SMEM4>>>(bo, gids, out);
}